// round 7
// baseline (speedup 1.0000x reference)
#include <cuda_runtime.h>
#include <cuda_bf16.h>
#include <math.h>

typedef __nv_bfloat16 bf16;
typedef unsigned long long u64;

// ---------------- problem constants ----------------
#define BB     2
#define CC     64
#define HH     256
#define WW     256
#define NPIX   65536        // H*W
#define NHEADS 8
#define DHEAD  8            // C/NH
#define C3     192          // 3*C
#define HID    170
#define G2     340          // 2*HID
#define GCH    64           // gram chunks over n
#define CHUNKN 1024         // n per gram chunk

// ---------------- scratch (device globals; no allocation allowed) ----------------
__device__ bf16  g_t   [(size_t)2 * BB * C3 * NPIX];   // qkv pre-dwconv (bf16)
__device__ bf16  g_qkv [(size_t)2 * BB * C3 * NPIX];   // qkv post-dwconv (bf16)
__device__ float g_xmid[(size_t)BB * CC * NPIX];       // x + cross (fp32 trunk)
__device__ bf16  g_t2  [(size_t)BB * G2 * NPIX];       // gdfn pre-dwconv (bf16)
__device__ bf16  g_gg  [(size_t)BB * HID * NPIX];      // gelu(x1)*x2 (bf16)
__device__ float g_part[(size_t)16 * GCH * 4 * 40];    // gram partials
__device__ float g_attn[(size_t)2 * BB * NHEADS * DHEAD * DHEAD];

// ---------------- packed fp32x2 helpers (Blackwell FFMA2) ----------------
#define FMA2(d, a, b, c) \
    asm("fma.rn.f32x2 %0, %1, %2, %3;" : "=l"(d) : "l"(a), "l"(b), "l"(c))

__device__ __forceinline__ u64 pk2(float lo, float hi) {
    u64 r; asm("mov.b64 %0, {%1, %2};" : "=l"(r) : "f"(lo), "f"(hi)); return r;
}
__device__ __forceinline__ void up2(float& lo, float& hi, u64 v) {
    asm("mov.b64 {%0, %1}, %2;" : "=f"(lo), "=f"(hi) : "l"(v));
}

__device__ __forceinline__ float dot4(float4 a, float4 b) {
    return a.x*b.x + a.y*b.y + a.z*b.z + a.w*b.w;
}
__device__ __forceinline__ void st4bf(bf16* p, float a, float b, float c, float d) {
    __nv_bfloat162 lo = __floats2bfloat162_rn(a, b);
    __nv_bfloat162 hi = __floats2bfloat162_rn(c, d);
    uint2 u;
    u.x = *reinterpret_cast<unsigned*>(&lo);
    u.y = *reinterpret_cast<unsigned*>(&hi);
    *reinterpret_cast<uint2*>(p) = u;
}
__device__ __forceinline__ float4 ld4bf(const bf16* p) {
    uint2 u = *reinterpret_cast<const uint2*>(p);
    __nv_bfloat162 lo = *reinterpret_cast<__nv_bfloat162*>(&u.x);
    __nv_bfloat162 hi = *reinterpret_cast<__nv_bfloat162*>(&u.y);
    float2 f0 = __bfloat1622float2(lo);
    float2 f1 = __bfloat1622float2(hi);
    return make_float4(f0.x, f0.y, f1.x, f1.y);
}

// ---------------- K1: fused channel-LN + 1x1 conv (C->3C), per stream ----------------
// block: 192 threads (one per out channel), tile of 128 pixels in smem.
// Inner GEMM uses packed f32x2 FMA: 1 broadcast LDS.128 : 2 FFMA2 (4 FMA).
__global__ __launch_bounds__(192) void k_ln_qkv(
    const float* __restrict__ x, const float* __restrict__ y,
    const float* __restrict__ ln11w, const float* __restrict__ ln11b,
    const float* __restrict__ ln12w, const float* __restrict__ ln12b,
    const float* __restrict__ qkvw)
{
    __shared__ __align__(16) float xs[CC * 128];
    const int b = blockIdx.y, s = blockIdx.z;
    const int n0 = blockIdx.x * 128;
    const float* src = s ? y : x;
    const float* lw  = s ? ln12w : ln11w;
    const float* lb  = s ? ln12b : ln11b;
    const int tid = threadIdx.x;

    if (tid < 128) {
        const int n = n0 + tid;
        float sum = 0.f, sq = 0.f;
        #pragma unroll 8
        for (int ch = 0; ch < CC; ch++) {
            float v = src[((size_t)b * CC + ch) * NPIX + n];
            xs[ch * 128 + tid] = v;
            sum += v; sq += v * v;
        }
        float mu  = sum * (1.f / CC);
        float var = sq * (1.f / CC) - mu * mu;
        float inv = rsqrtf(var + 1e-5f);
        #pragma unroll 8
        for (int ch = 0; ch < CC; ch++) {
            float v = xs[ch * 128 + tid];
            xs[ch * 128 + tid] = (v - mu) * inv * lw[ch] + lb[ch];
        }
    }
    const int oc = tid;
    u64 w2[CC];
    #pragma unroll
    for (int ch = 0; ch < CC; ch++) {
        float w = __ldg(&qkvw[oc * CC + ch]);
        w2[ch] = pk2(w, w);
    }
    __syncthreads();

    bf16* dst = &g_t[(((size_t)s * BB + b) * C3 + oc) * NPIX + n0];
    for (int p4 = 0; p4 < 32; p4++) {
        u64 a01 = 0, a23 = 0;
        #pragma unroll
        for (int ch = 0; ch < CC; ch++) {
            ulonglong2 xv = *reinterpret_cast<const ulonglong2*>(&xs[ch * 128 + p4 * 4]);
            FMA2(a01, w2[ch], xv.x, a01);
            FMA2(a23, w2[ch], xv.y, a23);
        }
        float f0, f1, f2, f3;
        up2(f0, f1, a01); up2(f2, f3, a23);
        st4bf(dst + p4 * 4, f0, f1, f2, f3);
    }
}

// ---------------- K2: tiled depthwise 3x3 on qkv ----------------
// block = 256 threads, tile = full 256-wide x 16-row strip of one channel.
// Staging via bf16x2 pair loads (half the LDG count vs scalar).
__global__ __launch_bounds__(256) void k_dw_qkv(const float* __restrict__ dw)
{
    __shared__ float s[18][258];
    const int sb = blockIdx.z;            // stream*B + b, flat
    const int ch = blockIdx.y;
    const int y0 = blockIdx.x * 16;
    const int tx = threadIdx.x;
    const bf16* in = &g_t[((size_t)sb * C3 + ch) * NPIX];

    float w[9];
    #pragma unroll
    for (int i = 0; i < 9; i++) w[i] = __ldg(&dw[ch * 9 + i]);

    // 18 rows x 128 column-pairs, flat over 256 threads (9 iters/thread)
    #pragma unroll 3
    for (int e = tx; e < 18 * 128; e += 256) {
        const int r  = e >> 7;
        const int cp = e & 127;
        const int gy = y0 + r - 1;
        float2 f = make_float2(0.f, 0.f);
        if ((unsigned)gy <= 255u) {
            __nv_bfloat162 v = *reinterpret_cast<const __nv_bfloat162*>(&in[gy * 256 + cp * 2]);
            f = __bfloat1622float2(v);
        }
        s[r][cp * 2 + 1] = f.x;
        s[r][cp * 2 + 2] = f.y;
    }
    if (tx < 18) { s[tx][0] = 0.f; s[tx][257] = 0.f; }
    __syncthreads();

    bf16* outp = &g_qkv[((size_t)sb * C3 + ch) * NPIX + y0 * 256 + tx];
    #pragma unroll 4
    for (int r = 0; r < 16; r++) {
        float acc =
            w[0] * s[r    ][tx    ] + w[1] * s[r    ][tx + 1] + w[2] * s[r    ][tx + 2] +
            w[3] * s[r + 1][tx    ] + w[4] * s[r + 1][tx + 1] + w[5] * s[r + 1][tx + 2] +
            w[6] * s[r + 2][tx    ] + w[7] * s[r + 2][tx + 1] + w[8] * s[r + 2][tx + 2];
        outp[r * 256] = __float2bfloat16(acc);
    }
}

// ---------------- K3: chunked Gram matrices + row sumsq (for l2norm) ----------------
// grid (GCH, 16 = b*h); block 128 = 4 warps; warp w owns c rows {2w, 2w+1}
__global__ __launch_bounds__(128) void k_gram()
{
    const int bh = blockIdx.y;
    const int b = bh >> 3, h = bh & 7;
    const int chunk = blockIdx.x;
    const int w = threadIdx.x >> 5, lane = threadIdx.x & 31;
    const int c0 = 2 * w, c1 = 2 * w + 1;

    const bf16* q0 = &g_qkv[(((size_t)0 * BB + b) * C3 +   0 + h * 8) * NPIX]; // q  (x)
    const bf16* k0 = &g_qkv[(((size_t)0 * BB + b) * C3 +  64 + h * 8) * NPIX]; // k  (x)
    const bf16* q1 = &g_qkv[(((size_t)1 * BB + b) * C3 +   0 + h * 8) * NPIX]; // q1 (y)
    const bf16* k1 = &g_qkv[(((size_t)1 * BB + b) * C3 +  64 + h * 8) * NPIX]; // k1 (y)

    float Sdu[2][8] = {}, Sud[2][8] = {};
    float nq1a = 0, nq1b = 0, nqa = 0, nqb = 0, nka = 0, nkb = 0, nk1a = 0, nk1b = 0;

    for (int it = 0; it < 8; it++) {
        const size_t n = (size_t)chunk * CHUNKN + it * 128 + lane * 4;
        float4 q1_0 = ld4bf(&q1[(size_t)c0 * NPIX + n]);
        float4 q1_1 = ld4bf(&q1[(size_t)c1 * NPIX + n]);
        float4 q_0  = ld4bf(&q0[(size_t)c0 * NPIX + n]);
        float4 q_1  = ld4bf(&q0[(size_t)c1 * NPIX + n]);
        float4 k_0  = ld4bf(&k0[(size_t)c0 * NPIX + n]);
        float4 k_1  = ld4bf(&k0[(size_t)c1 * NPIX + n]);
        float4 k1_0 = ld4bf(&k1[(size_t)c0 * NPIX + n]);
        float4 k1_1 = ld4bf(&k1[(size_t)c1 * NPIX + n]);
        nq1a += dot4(q1_0, q1_0); nq1b += dot4(q1_1, q1_1);
        nqa  += dot4(q_0,  q_0);  nqb  += dot4(q_1,  q_1);
        nka  += dot4(k_0,  k_0);  nkb  += dot4(k_1,  k_1);
        nk1a += dot4(k1_0, k1_0); nk1b += dot4(k1_1, k1_1);
        #pragma unroll
        for (int d = 0; d < 8; d++) {
            float4 kd  = ld4bf(&k0[(size_t)d * NPIX + n]);
            float4 k1d = ld4bf(&k1[(size_t)d * NPIX + n]);
            Sdu[0][d] += dot4(q1_0, kd);  Sdu[1][d] += dot4(q1_1, kd);
            Sud[0][d] += dot4(q_0, k1d);  Sud[1][d] += dot4(q_1, k1d);
        }
    }

    float acc[40];
    #pragma unroll
    for (int d = 0; d < 8; d++) {
        acc[d]      = Sdu[0][d]; acc[8 + d]  = Sdu[1][d];
        acc[16 + d] = Sud[0][d]; acc[24 + d] = Sud[1][d];
    }
    acc[32] = nq1a; acc[33] = nq1b; acc[34] = nqa;  acc[35] = nqb;
    acc[36] = nka;  acc[37] = nkb;  acc[38] = nk1a; acc[39] = nk1b;

    #pragma unroll
    for (int i = 0; i < 40; i++) {
        float v = acc[i];
        #pragma unroll
        for (int o = 16; o; o >>= 1) v += __shfl_xor_sync(0xffffffffu, v, o);
        if (lane == 0)
            g_part[(((size_t)bh * GCH + chunk) * 4 + w) * 40 + i] = v;
    }
}

// ---------------- K4: finalize attention (norms + temperature + softmax) ----------------
__global__ __launch_bounds__(128) void k_attn(const float* __restrict__ temp)
{
    __shared__ float sn[2][8][4][8];   // [b][h][type: q1,q,k,k1][c]
    const int tid = threadIdx.x;
    for (int e = tid; e < 512; e += 128) {
        int c = e & 7, t_ = (e >> 3) & 3, h = (e >> 5) & 7, b = e >> 8;
        int bh = b * 8 + h;
        float s = 0.f;
        for (int ch = 0; ch < GCH; ch++)
            s += g_part[(((size_t)bh * GCH + ch) * 4 + (c >> 1)) * 40 + 32 + t_ * 2 + (c & 1)];
        sn[b][h][t_][c] = fmaxf(sqrtf(s), 1e-12f);
    }
    __syncthreads();

    const int c = tid & 7, h = (tid >> 3) & 7, b = tid >> 6;
    const int bh = b * 8 + h;
    float Sdu[8] = {}, Sud[8] = {};
    for (int ch = 0; ch < GCH; ch++) {
        const float* p = &g_part[(((size_t)bh * GCH + ch) * 4 + (c >> 1)) * 40 + (c & 1) * 8];
        #pragma unroll
        for (int d = 0; d < 8; d++) { Sdu[d] += p[d]; Sud[d] += p[16 + d]; }
    }
    const float tmp = temp[h];

    float l[8], m = -1e30f;
    #pragma unroll
    for (int d = 0; d < 8; d++) {
        l[d] = Sdu[d] / (sn[b][h][0][c] * sn[b][h][2][d]) * tmp;
        m = fmaxf(m, l[d]);
    }
    float ssum = 0.f;
    #pragma unroll
    for (int d = 0; d < 8; d++) { l[d] = expf(l[d] - m); ssum += l[d]; }
    #pragma unroll
    for (int d = 0; d < 8; d++)
        g_attn[0 * 1024 + bh * 64 + c * 8 + d] = l[d] / ssum;

    m = -1e30f;
    #pragma unroll
    for (int d = 0; d < 8; d++) {
        l[d] = Sud[d] / (sn[b][h][1][c] * sn[b][h][3][d]) * tmp;
        m = fmaxf(m, l[d]);
    }
    ssum = 0.f;
    #pragma unroll
    for (int d = 0; d < 8; d++) { l[d] = expf(l[d] - m); ssum += l[d]; }
    #pragma unroll
    for (int d = 0; d < 8; d++)
        g_attn[1 * 1024 + bh * 64 + c * 8 + d] = l[d] / ssum;
}

// ---------------- K5: cross attention apply + residual (2 pixels/thread, f32x2) ----------------
__global__ __launch_bounds__(256) void k_cross(const float* __restrict__ x)
{
    __shared__ float adu[64], aud[64];
    const int bh = blockIdx.y;
    const int b = bh >> 3, h = bh & 7;
    const int tid = threadIdx.x;
    if (tid < 64)       adu[tid]      = g_attn[0 * 1024 + bh * 64 + tid];
    else if (tid < 128) aud[tid - 64] = g_attn[1 * 1024 + bh * 64 + tid - 64];
    __syncthreads();

    for (int i = 0; i < 2; i++) {
        const int n = blockIdx.x * 1024 + i * 512 + tid * 2;   // even pixel pair
        u64 v0[8], v1[8];
        #pragma unroll
        for (int d = 0; d < 8; d++) {
            __nv_bfloat162 a = *reinterpret_cast<const __nv_bfloat162*>(
                &g_qkv[(((size_t)0 * BB + b) * C3 + 128 + h * 8 + d) * NPIX + n]);
            __nv_bfloat162 c2 = *reinterpret_cast<const __nv_bfloat162*>(
                &g_qkv[(((size_t)1 * BB + b) * C3 + 128 + h * 8 + d) * NPIX + n]);
            float2 fa = __bfloat1622float2(a);
            float2 fc = __bfloat1622float2(c2);
            v0[d] = pk2(fa.x, fa.y);
            v1[d] = pk2(fc.x, fc.y);
        }
        #pragma unroll
        for (int cc2 = 0; cc2 < 8; cc2++) {
            u64 s2 = 0;
            #pragma unroll
            for (int d = 0; d < 8; d++) {
                float a0 = adu[cc2 * 8 + d], a1 = aud[cc2 * 8 + d];
                FMA2(s2, pk2(a0, a0), v0[d], s2);
                FMA2(s2, pk2(a1, a1), v1[d], s2);
            }
            float f0, f1;
            up2(f0, f1, s2);
            size_t idx = ((size_t)b * CC + h * 8 + cc2) * NPIX + n;
            float2 xv = *reinterpret_cast<const float2*>(&x[idx]);
            *reinterpret_cast<float2*>(&g_xmid[idx]) = make_float2(xv.x + f0, xv.y + f1);
        }
    }
}

// ---------------- K6: fused LN2 + 1x1 conv (C->2*HID) ----------------
__global__ __launch_bounds__(352) void k_ln_gdfn_in(
    const float* __restrict__ ln2w, const float* __restrict__ ln2b,
    const float* __restrict__ gw)
{
    __shared__ __align__(16) float xs[CC * 128];
    const int b = blockIdx.y;
    const int n0 = blockIdx.x * 128;
    const int tid = threadIdx.x;

    if (tid < 128) {
        const int n = n0 + tid;
        float sum = 0.f, sq = 0.f;
        #pragma unroll 8
        for (int ch = 0; ch < CC; ch++) {
            float v = g_xmid[((size_t)b * CC + ch) * NPIX + n];
            xs[ch * 128 + tid] = v;
            sum += v; sq += v * v;
        }
        float mu  = sum * (1.f / CC);
        float var = sq * (1.f / CC) - mu * mu;
        float inv = rsqrtf(var + 1e-5f);
        #pragma unroll 8
        for (int ch = 0; ch < CC; ch++) {
            float v = xs[ch * 128 + tid];
            xs[ch * 128 + tid] = (v - mu) * inv * ln2w[ch] + ln2b[ch];
        }
    }
    const int oc = tid;
    u64 w2[CC];
    if (oc < G2) {
        #pragma unroll
        for (int ch = 0; ch < CC; ch++) {
            float w = __ldg(&gw[oc * CC + ch]);
            w2[ch] = pk2(w, w);
        }
    }
    __syncthreads();
    if (oc >= G2) return;

    bf16* dst = &g_t2[(((size_t)b) * G2 + oc) * NPIX + n0];
    for (int p4 = 0; p4 < 32; p4++) {
        u64 a01 = 0, a23 = 0;
        #pragma unroll
        for (int ch = 0; ch < CC; ch++) {
            ulonglong2 xv = *reinterpret_cast<const ulonglong2*>(&xs[ch * 128 + p4 * 4]);
            FMA2(a01, w2[ch], xv.x, a01);
            FMA2(a23, w2[ch], xv.y, a23);
        }
        float f0, f1, f2, f3;
        up2(f0, f1, a01); up2(f2, f3, a23);
        st4bf(dst + p4 * 4, f0, f1, f2, f3);
    }
}

// ---------------- K7: tiled GDFN depthwise 3x3 on both halves + gelu gate ----------------
__global__ __launch_bounds__(256) void k_gdfn_dw(const float* __restrict__ dw)
{
    __shared__ float s1[18][258];
    __shared__ float s2[18][258];
    const int b = blockIdx.z, hc = blockIdx.y;
    const int y0 = blockIdx.x * 16;
    const int tx = threadIdx.x;
    const bf16* in1 = &g_t2[((size_t)b * G2 + hc) * NPIX];
    const bf16* in2 = &g_t2[((size_t)b * G2 + hc + HID) * NPIX];

    float wa[9], wb[9];
    #pragma unroll
    for (int i = 0; i < 9; i++) {
        wa[i] = __ldg(&dw[hc * 9 + i]);
        wb[i] = __ldg(&dw[(hc + HID) * 9 + i]);
    }

    // 18 rows x 128 column-pairs, flat over 256 threads, both planes
    #pragma unroll 3
    for (int e = tx; e < 18 * 128; e += 256) {
        const int r  = e >> 7;
        const int cp = e & 127;
        const int gy = y0 + r - 1;
        float2 f1v = make_float2(0.f, 0.f);
        float2 f2v = make_float2(0.f, 0.f);
        if ((unsigned)gy <= 255u) {
            __nv_bfloat162 v1 = *reinterpret_cast<const __nv_bfloat162*>(&in1[gy * 256 + cp * 2]);
            __nv_bfloat162 v2 = *reinterpret_cast<const __nv_bfloat162*>(&in2[gy * 256 + cp * 2]);
            f1v = __bfloat1622float2(v1);
            f2v = __bfloat1622float2(v2);
        }
        s1[r][cp * 2 + 1] = f1v.x; s1[r][cp * 2 + 2] = f1v.y;
        s2[r][cp * 2 + 1] = f2v.x; s2[r][cp * 2 + 2] = f2v.y;
    }
    if (tx < 18) { s1[tx][0] = 0.f; s1[tx][257] = 0.f; s2[tx][0] = 0.f; s2[tx][257] = 0.f; }
    __syncthreads();

    bf16* outp = &g_gg[((size_t)b * HID + hc) * NPIX + y0 * 256 + tx];
    #pragma unroll 2
    for (int r = 0; r < 16; r++) {
        float a =
            wa[0] * s1[r    ][tx    ] + wa[1] * s1[r    ][tx + 1] + wa[2] * s1[r    ][tx + 2] +
            wa[3] * s1[r + 1][tx    ] + wa[4] * s1[r + 1][tx + 1] + wa[5] * s1[r + 1][tx + 2] +
            wa[6] * s1[r + 2][tx    ] + wa[7] * s1[r + 2][tx + 1] + wa[8] * s1[r + 2][tx + 2];
        float g =
            wb[0] * s2[r    ][tx    ] + wb[1] * s2[r    ][tx + 1] + wb[2] * s2[r    ][tx + 2] +
            wb[3] * s2[r + 1][tx    ] + wb[4] * s2[r + 1][tx + 1] + wb[5] * s2[r + 1][tx + 2] +
            wb[6] * s2[r + 2][tx    ] + wb[7] * s2[r + 2][tx + 1] + wb[8] * s2[r + 2][tx + 2];
        float ge = a * normcdff(a);   // exact gelu: x * Phi(x)
        outp[r * 256] = __float2bfloat16(ge * g);
    }
}

// ---------------- K8: 1x1 conv (HID->C) + residual -> out ----------------
// ws transposed to [hc][oc]; inner loop uses packed f32x2 FMA over oc pairs.
__global__ __launch_bounds__(256) void k_gdfn_out(
    const float* __restrict__ wout, float* __restrict__ out)
{
    __shared__ __align__(16) float ws[HID * CC];    // 43.5 KB, [hc][oc]
    const int b = blockIdx.y;
    const int tid = threadIdx.x;
    for (int i = tid; i < CC * HID; i += 256) {
        int oc = i / HID, hc = i % HID;
        ws[hc * CC + oc] = wout[i];
    }
    __syncthreads();

    const int n = blockIdx.x * 256 + tid;
    u64 acc2[CC / 2];
    #pragma unroll
    for (int j = 0; j < CC / 2; j++) acc2[j] = 0;

    for (int hc = 0; hc < HID; hc++) {
        float gvf = __bfloat162float(g_gg[((size_t)b * HID + hc) * NPIX + n]);
        u64 gv2 = pk2(gvf, gvf);
        const ulonglong2* wr = reinterpret_cast<const ulonglong2*>(&ws[hc * CC]);
        #pragma unroll
        for (int j = 0; j < CC / 4; j++) {
            ulonglong2 wv = wr[j];
            FMA2(acc2[2 * j],     wv.x, gv2, acc2[2 * j]);
            FMA2(acc2[2 * j + 1], wv.y, gv2, acc2[2 * j + 1]);
        }
    }
    #pragma unroll
    for (int j = 0; j < CC / 2; j++) {
        float f0, f1;
        up2(f0, f1, acc2[j]);
        size_t i0 = ((size_t)b * CC + 2 * j) * NPIX + n;
        out[i0]        = g_xmid[i0]        + f0;
        out[i0 + NPIX] = g_xmid[i0 + NPIX] + f1;
    }
}

// ---------------- launch ----------------
extern "C" void kernel_launch(void* const* d_in, const int* in_sizes, int n_in,
                              void* d_out, int out_size)
{
    const float* x      = (const float*)d_in[0];
    const float* y      = (const float*)d_in[1];
    const float* ln11w  = (const float*)d_in[2];
    const float* ln11b  = (const float*)d_in[3];
    const float* ln12w  = (const float*)d_in[4];
    const float* ln12b  = (const float*)d_in[5];
    const float* ln2w   = (const float*)d_in[6];
    const float* ln2b   = (const float*)d_in[7];
    const float* qkvw   = (const float*)d_in[8];
    const float* qkvdw  = (const float*)d_in[9];
    const float* temp   = (const float*)d_in[10];
    const float* ginw   = (const float*)d_in[11];
    const float* gdw    = (const float*)d_in[12];
    const float* goutw  = (const float*)d_in[13];

    k_ln_qkv    <<<dim3(NPIX / 128, BB, 2), 192>>>(x, y, ln11w, ln11b, ln12w, ln12b, qkvw);
    k_dw_qkv    <<<dim3(HH / 16, C3, 2 * BB), 256>>>(qkvdw);
    k_gram      <<<dim3(GCH, 16), 128>>>();
    k_attn      <<<1, 128>>>(temp);
    k_cross     <<<dim3(NPIX / 1024, 16), 256>>>(x);
    k_ln_gdfn_in<<<dim3(NPIX / 128, BB), 352>>>(ln2w, ln2b, ginw);
    k_gdfn_dw   <<<dim3(HH / 16, HID, BB), 256>>>(gdw);
    k_gdfn_out  <<<dim3(NPIX / 256, BB), 256>>>(goutw, (float*)d_out);
}

// round 12
// speedup vs baseline: 1.3582x; 1.3582x over previous
#include <cuda_runtime.h>
#include <cuda_bf16.h>
#include <math.h>

typedef __nv_bfloat16 bf16;
typedef unsigned long long u64;

// ---------------- problem constants ----------------
#define BB     2
#define CC     64
#define HH     256
#define WW     256
#define NPIX   65536        // H*W
#define NHEADS 8
#define DHEAD  8            // C/NH
#define C3     192          // 3*C
#define HID    170
#define G2     340          // 2*HID
#define GCH    64           // gram chunks over n
#define CHUNKN 1024         // n per gram chunk

// ---------------- scratch (device globals; no allocation allowed) ----------------
__device__ bf16  g_t   [(size_t)2 * BB * C3 * NPIX];   // qkv pre-dwconv (bf16)
__device__ bf16  g_qkv [(size_t)2 * BB * C3 * NPIX];   // qkv post-dwconv (bf16)
__device__ float g_xmid[(size_t)BB * CC * NPIX];       // x + cross (fp32 trunk)
__device__ bf16  g_t2  [(size_t)BB * G2 * NPIX];       // gdfn pre-dwconv (bf16)
__device__ bf16  g_gg  [(size_t)BB * HID * NPIX];      // gelu(x1)*x2 (bf16)
__device__ float g_part[(size_t)16 * GCH * 4 * 40];    // gram partials
__device__ float g_attn[(size_t)2 * BB * NHEADS * DHEAD * DHEAD];

// ---------------- packed fp32x2 helpers (Blackwell FFMA2) ----------------
#define FMA2(d, a, b, c) \
    asm("fma.rn.f32x2 %0, %1, %2, %3;" : "=l"(d) : "l"(a), "l"(b), "l"(c))

__device__ __forceinline__ u64 pk2(float lo, float hi) {
    u64 r; asm("mov.b64 %0, {%1, %2};" : "=l"(r) : "f"(lo), "f"(hi)); return r;
}
__device__ __forceinline__ void up2(float& lo, float& hi, u64 v) {
    asm("mov.b64 {%0, %1}, %2;" : "=f"(lo), "=f"(hi) : "l"(v));
}

__device__ __forceinline__ float dot4(float4 a, float4 b) {
    return a.x*b.x + a.y*b.y + a.z*b.z + a.w*b.w;
}
__device__ __forceinline__ void st4bf(bf16* p, float a, float b, float c, float d) {
    __nv_bfloat162 lo = __floats2bfloat162_rn(a, b);
    __nv_bfloat162 hi = __floats2bfloat162_rn(c, d);
    uint2 u;
    u.x = *reinterpret_cast<unsigned*>(&lo);
    u.y = *reinterpret_cast<unsigned*>(&hi);
    *reinterpret_cast<uint2*>(p) = u;
}
__device__ __forceinline__ float4 ld4bf(const bf16* p) {
    uint2 u = *reinterpret_cast<const uint2*>(p);
    __nv_bfloat162 lo = *reinterpret_cast<__nv_bfloat162*>(&u.x);
    __nv_bfloat162 hi = *reinterpret_cast<__nv_bfloat162*>(&u.y);
    float2 f0 = __bfloat1622float2(lo);
    float2 f1 = __bfloat1622float2(hi);
    return make_float4(f0.x, f0.y, f1.x, f1.y);
}

// ---------------- K1: fused channel-LN + 1x1 conv (C->3C), per stream ----------------
// block 128 threads (4 warps). Warp-per-8-oc register tiling: lane owns 4 pixels,
// 16 u64 f32x2 accumulators; weights pre-duplicated in per-warp smem.
// Stores coalesced (warp writes 256B contiguous per oc).
__global__ __launch_bounds__(128) void k_ln_qkv(
    const float* __restrict__ x, const float* __restrict__ y,
    const float* __restrict__ ln11w, const float* __restrict__ ln11b,
    const float* __restrict__ ln12w, const float* __restrict__ ln12b,
    const float* __restrict__ qkvw)
{
    __shared__ __align__(16) float xs[CC * 128];   // 32 KB
    __shared__ __align__(16) u64 wsm[4][512];      // 16 KB: [warp][ch*8 + oc_l] duplicated
    const int b = blockIdx.y, s = blockIdx.z;
    const int n0 = blockIdx.x * 128;
    const float* src = s ? y : x;
    const float* lw  = s ? ln12w : ln11w;
    const float* lb  = s ? ln12b : ln11b;
    const int tid = threadIdx.x;
    const int w = tid >> 5, lane = tid & 31;

    {   // LN: one pixel per thread
        const int n = n0 + tid;
        float sum = 0.f, sq = 0.f;
        #pragma unroll 8
        for (int ch = 0; ch < CC; ch++) {
            float v = src[((size_t)b * CC + ch) * NPIX + n];
            xs[ch * 128 + tid] = v;
            sum += v; sq += v * v;
        }
        float mu  = sum * (1.f / CC);
        float var = sq * (1.f / CC) - mu * mu;
        float inv = rsqrtf(var + 1e-5f);
        #pragma unroll 8
        for (int ch = 0; ch < CC; ch++) {
            float v = xs[ch * 128 + tid];
            xs[ch * 128 + tid] = (v - mu) * inv * lw[ch] + lb[ch];
        }
    }
    __syncthreads();

    for (int task = w; task < 24; task += 4) {
        const int ocb = task * 8;
        // stage this task's 8x64 weights, duplicated as f32x2 pairs
        #pragma unroll
        for (int i = 0; i < 16; i++) {
            int idx = i * 32 + lane;                 // coalesced over gw
            int oc_l = idx >> 6, ch = idx & 63;
            float wv = __ldg(&qkvw[(ocb + oc_l) * CC + ch]);
            wsm[w][ch * 8 + oc_l] = pk2(wv, wv);
        }
        __syncwarp();

        u64 acc[8][2];
        #pragma unroll
        for (int l = 0; l < 8; l++) { acc[l][0] = 0; acc[l][1] = 0; }

        #pragma unroll 8
        for (int ch = 0; ch < CC; ch++) {
            ulonglong2 xv = *reinterpret_cast<const ulonglong2*>(&xs[ch * 128 + lane * 4]);
            const ulonglong2* wp = reinterpret_cast<const ulonglong2*>(&wsm[w][ch * 8]);
            ulonglong2 w01 = wp[0], w23 = wp[1], w45 = wp[2], w67 = wp[3];
            FMA2(acc[0][0], w01.x, xv.x, acc[0][0]); FMA2(acc[0][1], w01.x, xv.y, acc[0][1]);
            FMA2(acc[1][0], w01.y, xv.x, acc[1][0]); FMA2(acc[1][1], w01.y, xv.y, acc[1][1]);
            FMA2(acc[2][0], w23.x, xv.x, acc[2][0]); FMA2(acc[2][1], w23.x, xv.y, acc[2][1]);
            FMA2(acc[3][0], w23.y, xv.x, acc[3][0]); FMA2(acc[3][1], w23.y, xv.y, acc[3][1]);
            FMA2(acc[4][0], w45.x, xv.x, acc[4][0]); FMA2(acc[4][1], w45.x, xv.y, acc[4][1]);
            FMA2(acc[5][0], w45.y, xv.x, acc[5][0]); FMA2(acc[5][1], w45.y, xv.y, acc[5][1]);
            FMA2(acc[6][0], w67.x, xv.x, acc[6][0]); FMA2(acc[6][1], w67.x, xv.y, acc[6][1]);
            FMA2(acc[7][0], w67.y, xv.x, acc[7][0]); FMA2(acc[7][1], w67.y, xv.y, acc[7][1]);
        }

        #pragma unroll
        for (int l = 0; l < 8; l++) {
            int oc = ocb + l;
            bf16* dst = &g_t[(((size_t)s * BB + b) * C3 + oc) * NPIX + n0 + lane * 4];
            float f0, f1, f2, f3;
            up2(f0, f1, acc[l][0]); up2(f2, f3, acc[l][1]);
            st4bf(dst, f0, f1, f2, f3);
        }
        __syncwarp();
    }
}

// ---------------- K2: tiled depthwise 3x3 on qkv ----------------
__global__ __launch_bounds__(256) void k_dw_qkv(const float* __restrict__ dw)
{
    __shared__ float s[18][258];
    const int sb = blockIdx.z;            // stream*B + b, flat
    const int ch = blockIdx.y;
    const int y0 = blockIdx.x * 16;
    const int tx = threadIdx.x;
    const bf16* in = &g_t[((size_t)sb * C3 + ch) * NPIX];

    float w[9];
    #pragma unroll
    for (int i = 0; i < 9; i++) w[i] = __ldg(&dw[ch * 9 + i]);

    #pragma unroll 3
    for (int e = tx; e < 18 * 128; e += 256) {
        const int r  = e >> 7;
        const int cp = e & 127;
        const int gy = y0 + r - 1;
        float2 f = make_float2(0.f, 0.f);
        if ((unsigned)gy <= 255u) {
            __nv_bfloat162 v = *reinterpret_cast<const __nv_bfloat162*>(&in[gy * 256 + cp * 2]);
            f = __bfloat1622float2(v);
        }
        s[r][cp * 2 + 1] = f.x;
        s[r][cp * 2 + 2] = f.y;
    }
    if (tx < 18) { s[tx][0] = 0.f; s[tx][257] = 0.f; }
    __syncthreads();

    bf16* outp = &g_qkv[((size_t)sb * C3 + ch) * NPIX + y0 * 256 + tx];
    #pragma unroll 4
    for (int r = 0; r < 16; r++) {
        float acc =
            w[0] * s[r    ][tx    ] + w[1] * s[r    ][tx + 1] + w[2] * s[r    ][tx + 2] +
            w[3] * s[r + 1][tx    ] + w[4] * s[r + 1][tx + 1] + w[5] * s[r + 1][tx + 2] +
            w[6] * s[r + 2][tx    ] + w[7] * s[r + 2][tx + 1] + w[8] * s[r + 2][tx + 2];
        outp[r * 256] = __float2bfloat16(acc);
    }
}

// ---------------- K3: chunked Gram matrices + row sumsq (for l2norm) ----------------
__global__ __launch_bounds__(128) void k_gram()
{
    const int bh = blockIdx.y;
    const int b = bh >> 3, h = bh & 7;
    const int chunk = blockIdx.x;
    const int w = threadIdx.x >> 5, lane = threadIdx.x & 31;
    const int c0 = 2 * w, c1 = 2 * w + 1;

    const bf16* q0 = &g_qkv[(((size_t)0 * BB + b) * C3 +   0 + h * 8) * NPIX]; // q  (x)
    const bf16* k0 = &g_qkv[(((size_t)0 * BB + b) * C3 +  64 + h * 8) * NPIX]; // k  (x)
    const bf16* q1 = &g_qkv[(((size_t)1 * BB + b) * C3 +   0 + h * 8) * NPIX]; // q1 (y)
    const bf16* k1 = &g_qkv[(((size_t)1 * BB + b) * C3 +  64 + h * 8) * NPIX]; // k1 (y)

    float Sdu[2][8] = {}, Sud[2][8] = {};
    float nq1a = 0, nq1b = 0, nqa = 0, nqb = 0, nka = 0, nkb = 0, nk1a = 0, nk1b = 0;

    for (int it = 0; it < 8; it++) {
        const size_t n = (size_t)chunk * CHUNKN + it * 128 + lane * 4;
        float4 q1_0 = ld4bf(&q1[(size_t)c0 * NPIX + n]);
        float4 q1_1 = ld4bf(&q1[(size_t)c1 * NPIX + n]);
        float4 q_0  = ld4bf(&q0[(size_t)c0 * NPIX + n]);
        float4 q_1  = ld4bf(&q0[(size_t)c1 * NPIX + n]);
        float4 k_0  = ld4bf(&k0[(size_t)c0 * NPIX + n]);
        float4 k_1  = ld4bf(&k0[(size_t)c1 * NPIX + n]);
        float4 k1_0 = ld4bf(&k1[(size_t)c0 * NPIX + n]);
        float4 k1_1 = ld4bf(&k1[(size_t)c1 * NPIX + n]);
        nq1a += dot4(q1_0, q1_0); nq1b += dot4(q1_1, q1_1);
        nqa  += dot4(q_0,  q_0);  nqb  += dot4(q_1,  q_1);
        nka  += dot4(k_0,  k_0);  nkb  += dot4(k_1,  k_1);
        nk1a += dot4(k1_0, k1_0); nk1b += dot4(k1_1, k1_1);
        #pragma unroll
        for (int d = 0; d < 8; d++) {
            float4 kd  = ld4bf(&k0[(size_t)d * NPIX + n]);
            float4 k1d = ld4bf(&k1[(size_t)d * NPIX + n]);
            Sdu[0][d] += dot4(q1_0, kd);  Sdu[1][d] += dot4(q1_1, kd);
            Sud[0][d] += dot4(q_0, k1d);  Sud[1][d] += dot4(q_1, k1d);
        }
    }

    float acc[40];
    #pragma unroll
    for (int d = 0; d < 8; d++) {
        acc[d]      = Sdu[0][d]; acc[8 + d]  = Sdu[1][d];
        acc[16 + d] = Sud[0][d]; acc[24 + d] = Sud[1][d];
    }
    acc[32] = nq1a; acc[33] = nq1b; acc[34] = nqa;  acc[35] = nqb;
    acc[36] = nka;  acc[37] = nkb;  acc[38] = nk1a; acc[39] = nk1b;

    #pragma unroll
    for (int i = 0; i < 40; i++) {
        float v = acc[i];
        #pragma unroll
        for (int o = 16; o; o >>= 1) v += __shfl_xor_sync(0xffffffffu, v, o);
        if (lane == 0)
            g_part[(((size_t)bh * GCH + chunk) * 4 + w) * 40 + i] = v;
    }
}

// ---------------- K4: finalize attention (norms + temperature + softmax) ----------------
// One block per bh (16 blocks). Phase A: 160 threads each own one (w,i) scalar
// and sum the 64 chunk partials in parallel. Phase B: norms + softmax from smem
// (8 threads, one per attention row c in 0..7 — both directions).
__global__ __launch_bounds__(160) void k_attn(const float* __restrict__ temp)
{
    __shared__ float S[4][40];
    __shared__ float sn[4][8];     // [type: q1,q,k,k1][c]
    const int bh = blockIdx.x;
    const int h = bh & 7;
    const int t = threadIdx.x;

    {   // Phase A: parallel chunk reduction (160 outputs)
        const int w = t / 40, i = t % 40;
        const float* p = &g_part[((size_t)bh * GCH * 4 + w) * 40 + i];
        float s0 = 0.f;
        #pragma unroll 8
        for (int ch = 0; ch < GCH; ch++) s0 += p[(size_t)ch * 160];
        S[w][i] = s0;
    }
    __syncthreads();

    if (t < 32) {
        const int c = t & 7, t_ = t >> 3;
        sn[t_][c] = fmaxf(sqrtf(S[c >> 1][32 + t_ * 2 + (c & 1)]), 1e-12f);
    }
    __syncthreads();

    if (t < 8) {
        const int c = t;               // attention row 0..7
        const float tmp = temp[h];
        const float* row = &S[c >> 1][(c & 1) * 8];

        float l[8], m = -1e30f;
        #pragma unroll
        for (int d = 0; d < 8; d++) {
            l[d] = row[d] / (sn[0][c] * sn[2][d]) * tmp;
            m = fmaxf(m, l[d]);
        }
        float ssum = 0.f;
        #pragma unroll
        for (int d = 0; d < 8; d++) { l[d] = expf(l[d] - m); ssum += l[d]; }
        #pragma unroll
        for (int d = 0; d < 8; d++)
            g_attn[0 * 1024 + bh * 64 + c * 8 + d] = l[d] / ssum;

        m = -1e30f;
        #pragma unroll
        for (int d = 0; d < 8; d++) {
            l[d] = row[16 + d] / (sn[1][c] * sn[3][d]) * tmp;
            m = fmaxf(m, l[d]);
        }
        ssum = 0.f;
        #pragma unroll
        for (int d = 0; d < 8; d++) { l[d] = expf(l[d] - m); ssum += l[d]; }
        #pragma unroll
        for (int d = 0; d < 8; d++)
            g_attn[1 * 1024 + bh * 64 + c * 8 + d] = l[d] / ssum;
    }
}

// ---------------- K5: cross attention apply + residual (2 pixels/thread, f32x2) ----------------
// Attention matrices pre-duplicated in smem as packed f32x2 pairs:
// inner loop is 2 LDS.64 + 2 FFMA2 per d (no per-iteration repacking).
__global__ __launch_bounds__(256) void k_cross(const float* __restrict__ x)
{
    __shared__ __align__(16) u64 adu2[64], aud2[64];
    const int bh = blockIdx.y;
    const int b = bh >> 3, h = bh & 7;
    const int tid = threadIdx.x;
    if (tid < 64) {
        float a = g_attn[0 * 1024 + bh * 64 + tid];
        adu2[tid] = pk2(a, a);
    } else if (tid < 128) {
        float a = g_attn[1 * 1024 + bh * 64 + tid - 64];
        aud2[tid - 64] = pk2(a, a);
    }
    __syncthreads();

    for (int i = 0; i < 2; i++) {
        const int n = blockIdx.x * 1024 + i * 512 + tid * 2;   // even pixel pair
        u64 v0[8], v1[8];
        #pragma unroll
        for (int d = 0; d < 8; d++) {
            __nv_bfloat162 a = *reinterpret_cast<const __nv_bfloat162*>(
                &g_qkv[(((size_t)0 * BB + b) * C3 + 128 + h * 8 + d) * NPIX + n]);
            __nv_bfloat162 c2 = *reinterpret_cast<const __nv_bfloat162*>(
                &g_qkv[(((size_t)1 * BB + b) * C3 + 128 + h * 8 + d) * NPIX + n]);
            float2 fa = __bfloat1622float2(a);
            float2 fc = __bfloat1622float2(c2);
            v0[d] = pk2(fa.x, fa.y);
            v1[d] = pk2(fc.x, fc.y);
        }
        #pragma unroll
        for (int cc2 = 0; cc2 < 8; cc2++) {
            u64 s2 = 0;
            #pragma unroll
            for (int d = 0; d < 8; d++) {
                FMA2(s2, adu2[cc2 * 8 + d], v0[d], s2);
                FMA2(s2, aud2[cc2 * 8 + d], v1[d], s2);
            }
            float f0, f1;
            up2(f0, f1, s2);
            size_t idx = ((size_t)b * CC + h * 8 + cc2) * NPIX + n;
            float2 xv = *reinterpret_cast<const float2*>(&x[idx]);
            *reinterpret_cast<float2*>(&g_xmid[idx]) = make_float2(xv.x + f0, xv.y + f1);
        }
    }
}

// ---------------- K6: fused LN2 + 1x1 conv (C->2*HID), warp-tiled like K1 ----------------
__global__ __launch_bounds__(128) void k_ln_gdfn_in(
    const float* __restrict__ ln2w, const float* __restrict__ ln2b,
    const float* __restrict__ gw)
{
    __shared__ __align__(16) float xs[CC * 128];   // 32 KB
    __shared__ __align__(16) u64 wsm[4][512];      // 16 KB
    const int b = blockIdx.y;
    const int n0 = blockIdx.x * 128;
    const int tid = threadIdx.x;
    const int w = tid >> 5, lane = tid & 31;

    {   // LN
        const int n = n0 + tid;
        float sum = 0.f, sq = 0.f;
        #pragma unroll 8
        for (int ch = 0; ch < CC; ch++) {
            float v = g_xmid[((size_t)b * CC + ch) * NPIX + n];
            xs[ch * 128 + tid] = v;
            sum += v; sq += v * v;
        }
        float mu  = sum * (1.f / CC);
        float var = sq * (1.f / CC) - mu * mu;
        float inv = rsqrtf(var + 1e-5f);
        #pragma unroll 8
        for (int ch = 0; ch < CC; ch++) {
            float v = xs[ch * 128 + tid];
            xs[ch * 128 + tid] = (v - mu) * inv * ln2w[ch] + ln2b[ch];
        }
    }
    __syncthreads();

    for (int task = w; task < 43; task += 4) {      // 43 groups cover 344 >= G2
        const int ocb = task * 8;
        #pragma unroll
        for (int i = 0; i < 16; i++) {
            int idx = i * 32 + lane;
            int oc_l = idx >> 6, ch = idx & 63;
            int oc = ocb + oc_l;
            float wv = (oc < G2) ? __ldg(&gw[oc * CC + ch]) : 0.f;
            wsm[w][ch * 8 + oc_l] = pk2(wv, wv);
        }
        __syncwarp();

        u64 acc[8][2];
        #pragma unroll
        for (int l = 0; l < 8; l++) { acc[l][0] = 0; acc[l][1] = 0; }

        #pragma unroll 8
        for (int ch = 0; ch < CC; ch++) {
            ulonglong2 xv = *reinterpret_cast<const ulonglong2*>(&xs[ch * 128 + lane * 4]);
            const ulonglong2* wp = reinterpret_cast<const ulonglong2*>(&wsm[w][ch * 8]);
            ulonglong2 w01 = wp[0], w23 = wp[1], w45 = wp[2], w67 = wp[3];
            FMA2(acc[0][0], w01.x, xv.x, acc[0][0]); FMA2(acc[0][1], w01.x, xv.y, acc[0][1]);
            FMA2(acc[1][0], w01.y, xv.x, acc[1][0]); FMA2(acc[1][1], w01.y, xv.y, acc[1][1]);
            FMA2(acc[2][0], w23.x, xv.x, acc[2][0]); FMA2(acc[2][1], w23.x, xv.y, acc[2][1]);
            FMA2(acc[3][0], w23.y, xv.x, acc[3][0]); FMA2(acc[3][1], w23.y, xv.y, acc[3][1]);
            FMA2(acc[4][0], w45.x, xv.x, acc[4][0]); FMA2(acc[4][1], w45.x, xv.y, acc[4][1]);
            FMA2(acc[5][0], w45.y, xv.x, acc[5][0]); FMA2(acc[5][1], w45.y, xv.y, acc[5][1]);
            FMA2(acc[6][0], w67.x, xv.x, acc[6][0]); FMA2(acc[6][1], w67.x, xv.y, acc[6][1]);
            FMA2(acc[7][0], w67.y, xv.x, acc[7][0]); FMA2(acc[7][1], w67.y, xv.y, acc[7][1]);
        }

        #pragma unroll
        for (int l = 0; l < 8; l++) {
            int oc = ocb + l;
            if (oc < G2) {
                bf16* dst = &g_t2[(((size_t)b) * G2 + oc) * NPIX + n0 + lane * 4];
                float f0, f1, f2, f3;
                up2(f0, f1, acc[l][0]); up2(f2, f3, acc[l][1]);
                st4bf(dst, f0, f1, f2, f3);
            }
        }
        __syncwarp();
    }
}

// ---------------- K7: tiled GDFN depthwise 3x3 on both halves + gelu gate ----------------
__global__ __launch_bounds__(256) void k_gdfn_dw(const float* __restrict__ dw)
{
    __shared__ float s1[18][258];
    __shared__ float s2[18][258];
    const int b = blockIdx.z, hc = blockIdx.y;
    const int y0 = blockIdx.x * 16;
    const int tx = threadIdx.x;
    const bf16* in1 = &g_t2[((size_t)b * G2 + hc) * NPIX];
    const bf16* in2 = &g_t2[((size_t)b * G2 + hc + HID) * NPIX];

    float wa[9], wb[9];
    #pragma unroll
    for (int i = 0; i < 9; i++) {
        wa[i] = __ldg(&dw[hc * 9 + i]);
        wb[i] = __ldg(&dw[(hc + HID) * 9 + i]);
    }

    #pragma unroll 3
    for (int e = tx; e < 18 * 128; e += 256) {
        const int r  = e >> 7;
        const int cp = e & 127;
        const int gy = y0 + r - 1;
        float2 f1v = make_float2(0.f, 0.f);
        float2 f2v = make_float2(0.f, 0.f);
        if ((unsigned)gy <= 255u) {
            __nv_bfloat162 v1 = *reinterpret_cast<const __nv_bfloat162*>(&in1[gy * 256 + cp * 2]);
            __nv_bfloat162 v2 = *reinterpret_cast<const __nv_bfloat162*>(&in2[gy * 256 + cp * 2]);
            f1v = __bfloat1622float2(v1);
            f2v = __bfloat1622float2(v2);
        }
        s1[r][cp * 2 + 1] = f1v.x; s1[r][cp * 2 + 2] = f1v.y;
        s2[r][cp * 2 + 1] = f2v.x; s2[r][cp * 2 + 2] = f2v.y;
    }
    if (tx < 18) { s1[tx][0] = 0.f; s1[tx][257] = 0.f; s2[tx][0] = 0.f; s2[tx][257] = 0.f; }
    __syncthreads();

    bf16* outp = &g_gg[((size_t)b * HID + hc) * NPIX + y0 * 256 + tx];
    #pragma unroll 2
    for (int r = 0; r < 16; r++) {
        float a =
            wa[0] * s1[r    ][tx    ] + wa[1] * s1[r    ][tx + 1] + wa[2] * s1[r    ][tx + 2] +
            wa[3] * s1[r + 1][tx    ] + wa[4] * s1[r + 1][tx + 1] + wa[5] * s1[r + 1][tx + 2] +
            wa[6] * s1[r + 2][tx    ] + wa[7] * s1[r + 2][tx + 1] + wa[8] * s1[r + 2][tx + 2];
        float g =
            wb[0] * s2[r    ][tx    ] + wb[1] * s2[r    ][tx + 1] + wb[2] * s2[r    ][tx + 2] +
            wb[3] * s2[r + 1][tx    ] + wb[4] * s2[r + 1][tx + 1] + wb[5] * s2[r + 1][tx + 2] +
            wb[6] * s2[r + 2][tx    ] + wb[7] * s2[r + 2][tx + 1] + wb[8] * s2[r + 2][tx + 2];
        float ge = a * normcdff(a);   // exact gelu: x * Phi(x)
        outp[r * 256] = __float2bfloat16(ge * g);
    }
}

// ---------------- K8: 1x1 conv (HID->C) + residual -> out ----------------
__global__ __launch_bounds__(256) void k_gdfn_out(
    const float* __restrict__ wout, float* __restrict__ out)
{
    __shared__ __align__(16) float ws[HID * CC];    // 43.5 KB, [hc][oc]
    const int b = blockIdx.y;
    const int tid = threadIdx.x;
    for (int i = tid; i < CC * HID; i += 256) {
        int oc = i / HID, hc = i % HID;
        ws[hc * CC + oc] = wout[i];
    }
    __syncthreads();

    const int n = blockIdx.x * 256 + tid;
    u64 acc2[CC / 2];
    #pragma unroll
    for (int j = 0; j < CC / 2; j++) acc2[j] = 0;

    for (int hc = 0; hc < HID; hc++) {
        float gvf = __bfloat162float(g_gg[((size_t)b * HID + hc) * NPIX + n]);
        u64 gv2 = pk2(gvf, gvf);
        const ulonglong2* wr = reinterpret_cast<const ulonglong2*>(&ws[hc * CC]);
        #pragma unroll
        for (int j = 0; j < CC / 4; j++) {
            ulonglong2 wv = wr[j];
            FMA2(acc2[2 * j],     wv.x, gv2, acc2[2 * j]);
            FMA2(acc2[2 * j + 1], wv.y, gv2, acc2[2 * j + 1]);
        }
    }
    #pragma unroll
    for (int j = 0; j < CC / 2; j++) {
        float f0, f1;
        up2(f0, f1, acc2[j]);
        size_t i0 = ((size_t)b * CC + 2 * j) * NPIX + n;
        out[i0]        = g_xmid[i0]        + f0;
        out[i0 + NPIX] = g_xmid[i0 + NPIX] + f1;
    }
}

// ---------------- launch ----------------
extern "C" void kernel_launch(void* const* d_in, const int* in_sizes, int n_in,
                              void* d_out, int out_size)
{
    const float* x      = (const float*)d_in[0];
    const float* y      = (const float*)d_in[1];
    const float* ln11w  = (const float*)d_in[2];
    const float* ln11b  = (const float*)d_in[3];
    const float* ln12w  = (const float*)d_in[4];
    const float* ln12b  = (const float*)d_in[5];
    const float* ln2w   = (const float*)d_in[6];
    const float* ln2b   = (const float*)d_in[7];
    const float* qkvw   = (const float*)d_in[8];
    const float* qkvdw  = (const float*)d_in[9];
    const float* temp   = (const float*)d_in[10];
    const float* ginw   = (const float*)d_in[11];
    const float* gdw    = (const float*)d_in[12];
    const float* goutw  = (const float*)d_in[13];

    k_ln_qkv    <<<dim3(NPIX / 128, BB, 2), 128>>>(x, y, ln11w, ln11b, ln12w, ln12b, qkvw);
    k_dw_qkv    <<<dim3(HH / 16, C3, 2 * BB), 256>>>(qkvdw);
    k_gram      <<<dim3(GCH, 16), 128>>>();
    k_attn      <<<16, 160>>>(temp);
    k_cross     <<<dim3(NPIX / 1024, 16), 256>>>(x);
    k_ln_gdfn_in<<<dim3(NPIX / 128, BB), 128>>>(ln2w, ln2b, ginw);
    k_gdfn_dw   <<<dim3(HH / 16, HID, BB), 256>>>(gdw);
    k_gdfn_out  <<<dim3(NPIX / 256, BB), 256>>>(goutw, (float*)d_out);
}